// round 17
// baseline (speedup 1.0000x reference)
#include <cuda_runtime.h>
#include <cuda_fp16.h>
#include <math.h>
#include <stdint.h>

#define N_NODES 20000
#define N_EDGES 320000
#define KMIX    5
#define FIN     256
#define FOUT    128
#define KO      (KMIX*FOUT)   /* 640 */
#define MASKW   (FIN/32)      /* 8 */
#define NPB     8             /* nodes per block in prep_x */
#define PREPB   (N_NODES/NPB) /* 2500 prep blocks */
#define CNTB    ((N_EDGES + 255)/256) /* 1250 count blocks */
#define NTILES  157           /* M tiles of 128 rows */
#define NPADR   (NTILES*128)  /* 20096 padded rows */

// ---------------- static device scratch (no allocs allowed) ----------------
static __device__ __align__(16) half     g_X0h[N_NODES*FIN];
static __device__ __align__(16) unsigned g_mask[N_NODES*MASKW];
static __device__ __align__(16) float    g_gamma[KMIX*N_NODES];
static __device__ __align__(16) float    g_invvar[KMIX*FIN];
static __device__ __align__(16) float    g_dinv[N_NODES];
static __device__ __align__(16) int      g_cnt[N_NODES];
static __device__ __align__(16) int      g_rowptr[N_NODES+1];
static __device__ __align__(16) int      g_wpos[N_NODES];
static __device__ __align__(16) int      g_ccol[N_EDGES];
static __device__ __align__(16) float    g_swn[N_NODES];
static __device__ int g_total;
// fp16 A matrices: chunk-major pre-swizzled [kc][tile][16KB image], padded
static __device__ __align__(16) half     g_G1[(size_t)NPADR*FIN];
static __device__ __align__(16) half     g_G2[(size_t)NPADR*FIN];
static __device__ __align__(16) half     g_G3[(size_t)NPADR*FIN];
// fp16 weights: B-tile-major pre-swizzled [(col_block*4+kc)][8KB image]
static __device__ __align__(16) half     g_Wt [FOUT*FIN];
static __device__ __align__(16) half     g_Wmt[KO*FIN];
static __device__ __align__(16) half     g_Wct[KO*FIN];
// fp16 c1 = G1 @ W (row-major)
static __device__ __align__(16) half     g_C1[N_NODES*FOUT];
// fp16 per-component partials (replaces output atomics)
static __device__ __align__(16) half     g_Part[(size_t)KMIX*N_NODES*FOUT];
static __device__ int g_is64;

// ================= helpers =================================================
__device__ __forceinline__ uint32_t smem_u32(const void* p) {
    uint32_t a;
    asm("{ .reg .u64 t; cvta.to.shared.u64 t, %1; cvt.u32.u64 %0, t; }" : "=r"(a) : "l"(p));
    return a;
}
#define SW128(o) ((o) ^ (((o) >> 3) & 0x70))

__device__ __forceinline__ void ldsm_x4(uint32_t* r, uint32_t addr) {
    asm volatile("ldmatrix.sync.aligned.m8n8.x4.shared.b16 {%0,%1,%2,%3}, [%4];"
                 : "=r"(r[0]), "=r"(r[1]), "=r"(r[2]), "=r"(r[3]) : "r"(addr));
}
__device__ __forceinline__ void mma_fp16(float* c, const uint32_t* a,
                                         uint32_t b0, uint32_t b1) {
    asm volatile(
        "mma.sync.aligned.m16n8k16.row.col.f32.f16.f16.f32 "
        "{%0,%1,%2,%3},{%4,%5,%6,%7},{%8,%9},{%0,%1,%2,%3};"
        : "+f"(c[0]), "+f"(c[1]), "+f"(c[2]), "+f"(c[3])
        : "r"(a[0]), "r"(a[1]), "r"(a[2]), "r"(a[3]), "r"(b0), "r"(b1));
}
// bulk async copy global->shared with mbarrier completion
__device__ __forceinline__ void bulk_g2s(uint32_t dst, const void* src,
                                         uint32_t bytes, uint32_t mbar) {
    asm volatile(
        "cp.async.bulk.shared::cta.global.mbarrier::complete_tx::bytes [%0], [%1], %2, [%3];"
        :: "r"(dst), "l"(src), "r"(bytes), "r"(mbar) : "memory");
}
#define MBAR_INIT(mb, c) asm volatile("mbarrier.init.shared.b64 [%0], %1;" :: "r"(mb), "r"((uint32_t)(c)) : "memory")
#define MBAR_EXPTX(mb, n) asm volatile("mbarrier.arrive.expect_tx.shared.b64 _, [%0], %1;" :: "r"(mb), "r"((uint32_t)(n)) : "memory")
__device__ __forceinline__ void mbar_wait(uint32_t mb, uint32_t parity) {
    asm volatile(
        "{\n\t.reg .pred P1;\n\t"
        "WAIT_LOOP_%=:\n\t"
        "mbarrier.try_wait.parity.acquire.cta.shared::cta.b64 P1, [%0], %1, 0x989680;\n\t"
        "@P1 bra.uni WAIT_DONE_%=;\n\t"
        "bra.uni WAIT_LOOP_%=;\n\t"
        "WAIT_DONE_%=:\n\t}"
        :: "r"(mb), "r"(parity) : "memory");
}

__device__ __forceinline__ int load_row(const void* ei, int e) {
    if (g_is64) return (int)((const long long*)ei)[e];
    return ((const int*)ei)[e];
}
__device__ __forceinline__ int load_col(const void* ei, int e) {
    if (g_is64) return (int)((const long long*)ei)[N_EDGES + e];
    return ((const int*)ei)[N_EDGES + e];
}

// ---------------- merged setup: dtype + weights(swizzled) + cnt ------------
__global__ void setup_all(const int* __restrict__ ei32,
                          const float* __restrict__ means,
                          const float* __restrict__ logvars,
                          const float* __restrict__ W) {
    int idx = blockIdx.x * blockDim.x + threadIdx.x;
    if (idx == 0) {
        int is64 = 1;
        for (int i = 0; i < 128; i++)
            if (ei32[2*i + 1] != 0) { is64 = 0; break; }
        g_is64 = is64;
        g_total = 0;
    }
    if (idx < N_NODES) g_cnt[idx] = 0;
    if (idx < KMIX*FIN) g_invvar[idx] = expf(-logvars[idx]);
    if (idx < KO*FIN) {
        int j = idx / FIN, i = idx % FIN;               // j = col (k*FOUT+o), i = K
        int k = j / FOUT, o = j % FOUT;
        int cb = j >> 6, cl = j & 63, kc = i >> 6, il = i & 63;
        size_t boff = ((size_t)(cb*4 + kc)) * 8192
                    + SW128((uint32_t)(cl*128 + (il >> 3)*16)) + (il & 7)*2;
        float w = W[i*FOUT + o];
        *(half*)((char*)g_Wmt + boff) = __float2half_rn(means[k*FIN + i] * w);
        *(half*)((char*)g_Wct + boff) = __float2half_rn(expf(logvars[k*FIN + i]) * w * w);
        if (j < FOUT) {
            *(half*)((char*)g_Wt + boff) = __float2half_rn(W[i*FOUT + j]);
        }
    }
}

// ---------------- fused prep_x (float2) + count_deg ------------------------
__global__ __launch_bounds__(FIN) void prep_and_count(const float* __restrict__ x,
                       const float* __restrict__ means,
                       const float* __restrict__ logp,
                       const void* __restrict__ ei) {
    if (blockIdx.x >= PREPB) {
        int e = (blockIdx.x - PREPB) * 256 + threadIdx.x;
        if (e < N_EDGES) atomicAdd(&g_cnt[load_row(ei, e)], 1);
        return;
    }
    int t = threadIdx.x;
    int h = t >> 7;
    int tt = t & 127;
    int lane = t & 31;
    int wp = tt >> 5;
    int nbase = blockIdx.x * NPB;

    float mk0[KMIX], mk1[KMIX], iv0[KMIX], iv1[KMIX];
#pragma unroll
    for (int k = 0; k < KMIX; k++) {
        mk0[k] = means[k*FIN + 2*tt];
        mk1[k] = means[k*FIN + 2*tt + 1];
        iv0[k] = g_invvar[k*FIN + 2*tt];
        iv1[k] = g_invvar[k*FIN + 2*tt + 1];
    }

    __shared__ float red[NPB][4][KMIX];
    __shared__ float lpv[KMIX];
    if (t < KMIX) lpv[t] = logp[t];

#pragma unroll
    for (int it = 0; it < 4; it++) {
        int n = nbase + 2*it + h;
        float2 v = *(const float2*)(x + (size_t)n*FIN + 2*tt);
        bool i0 = !(v.x == v.x), i1 = !(v.y == v.y);
        ((__half2*)g_X0h)[(size_t)n*(FIN/2) + tt] =
            __floats2half2_rn(i0 ? 0.f : v.x, i1 ? 0.f : v.y);
        unsigned b0 = __ballot_sync(0xffffffffu, i0);
        unsigned b1 = __ballot_sync(0xffffffffu, i1);
        if (lane == 0) {
            g_mask[n*MASKW + 2*wp]     = b0;
            g_mask[n*MASKW + 2*wp + 1] = b1;
        }
        float d[KMIX];
#pragma unroll
        for (int k = 0; k < KMIX; k++) {
            float f0 = i0 ? 0.f : (v.x - mk0[k]);
            float f1 = i1 ? 0.f : (v.y - mk1[k]);
            d[k] = f0*f0*iv0[k] + f1*f1*iv1[k];
        }
#pragma unroll
        for (int k = 0; k < KMIX; k++)
            for (int off = 16; off > 0; off >>= 1)
                d[k] += __shfl_down_sync(0xffffffffu, d[k], off);
        if (lane == 0)
            for (int k = 0; k < KMIX; k++) red[2*it + h][wp][k] = d[k];
    }
    __syncthreads();
    if (t < NPB) {
        int n = nbase + t;
        float s[KMIX], m = -1e30f;
#pragma unroll
        for (int k = 0; k < KMIX; k++) {
            float acc = 0.f;
            for (int ww = 0; ww < 4; ww++) acc += red[t][ww][k];
            s[k] = lpv[k] - 0.5f * acc;
            m = fmaxf(m, s[k]);
        }
        float ssum = 0.f, e[KMIX];
#pragma unroll
        for (int k = 0; k < KMIX; k++) { e[k] = expf(s[k] - m); ssum += e[k]; }
        float inv = 1.f / ssum;
#pragma unroll
        for (int k = 0; k < KMIX; k++) g_gamma[k*N_NODES + n] = e[k] * inv;
    }
}

// ---------------- CSR build ------------------------------------------------
__global__ __launch_bounds__(256) void compute_offsets() {
    __shared__ int wsums[8];
    __shared__ int blockbase;
    int i = blockIdx.x * 256 + threadIdx.x;
    int lane = threadIdx.x & 31, w = threadIdx.x >> 5;
    int v = (i < N_NODES) ? g_cnt[i] : 0;
    int xv = v;
#pragma unroll
    for (int off = 1; off < 32; off <<= 1) {
        int y = __shfl_up_sync(0xffffffffu, xv, off);
        if (lane >= off) xv += y;
    }
    if (lane == 31) wsums[w] = xv;
    __syncthreads();
    if (threadIdx.x == 0) {
        int s = 0;
#pragma unroll
        for (int j = 0; j < 8; j++) { int tv = wsums[j]; wsums[j] = s; s += tv; }
        blockbase = atomicAdd(&g_total, s);
    }
    __syncthreads();
    if (i < N_NODES) {
        int start = blockbase + wsums[w] + (xv - v);
        g_rowptr[i] = start;
        g_wpos[i]   = start;
        g_dinv[i]   = rsqrtf((float)(v + 1));
    }
}

__global__ void scatter_edges(const void* __restrict__ ei) {
    int tid0 = blockIdx.x * blockDim.x + threadIdx.x;
#pragma unroll
    for (int hh = 0; hh < 2; hh++) {
        int e = tid0 + hh * (N_EDGES/2);
        int r = load_row(ei, e);
        int c = load_col(ei, e);
        int p = atomicAdd(&g_wpos[r], 1);
        g_ccol[p] = c;
    }
}

// ---------------- fused SpMM -> chunk-major swizzled G1/G2/G3 --------------
__global__ __launch_bounds__(128) void spmm_kernel() {
    int r = blockIdx.x;
    int t = threadIdx.x;
    int p = t >> 5;
    int l = t & 31;
    float dr = g_dinv[r];
    int start = g_rowptr[r], end = start + g_cnt[r];
    float a1x=0.f, a1y=0.f, a2x=0.f, a2y=0.f, a3x=0.f, a3y=0.f, sw=0.f;
    const __half2* X = (const __half2*)g_X0h;

    int e = start;
    for (; e + 8 <= end; e += 8) {
        int   c[8]; float d[8]; float2 xv[8]; uint2 mm[8];
#pragma unroll
        for (int q = 0; q < 8; q++) c[q] = g_ccol[e + q];
#pragma unroll
        for (int q = 0; q < 8; q++) d[q] = g_dinv[c[q]];
#pragma unroll
        for (int q = 0; q < 8; q++) xv[q] = __half22float2(X[c[q]*(FIN/2) + t]);
#pragma unroll
        for (int q = 0; q < 8; q++) mm[q] = *(const uint2*)&g_mask[c[q]*MASKW + 2*p];
#pragma unroll
        for (int q = 0; q < 8; q++) {
            a1x += d[q]*xv[q].x; a1y += d[q]*xv[q].y;
            if ((mm[q].x >> l) & 1u) { a2x += d[q]; a3x += d[q]*d[q]; }
            if ((mm[q].y >> l) & 1u) { a2y += d[q]; a3y += d[q]*d[q]; }
            sw += d[q];
        }
    }
    for (; e < end; e++) {
        int c0 = g_ccol[e];
        float d0 = g_dinv[c0];
        float2 x0 = __half22float2(X[c0*(FIN/2) + t]);
        uint2 m0 = *(const uint2*)&g_mask[c0*MASKW + 2*p];
        a1x += d0*x0.x; a1y += d0*x0.y;
        if ((m0.x >> l) & 1u) { a2x += d0; a3x += d0*d0; }
        if ((m0.y >> l) & 1u) { a2y += d0; a3y += d0*d0; }
        sw += d0;
    }
    {   // self loop
        float2 xr = __half22float2(X[r*(FIN/2) + t]);
        uint2 mr = *(const uint2*)&g_mask[r*MASKW + 2*p];
        a1x += dr*xr.x; a1y += dr*xr.y;
        if ((mr.x >> l) & 1u) { a2x += dr; a3x += dr*dr; }
        if ((mr.y >> l) & 1u) { a2y += dr; a3y += dr*dr; }
        sw += dr;
    }
    int tile = r >> 7, rloc = r & 127;
    int kc = t >> 5, pp = t & 31;
    size_t off = ((size_t)kc * NTILES + tile) * 16384
               + SW128((uint32_t)(rloc*128 + (pp >> 2)*16)) + (pp & 3)*4;
    float dr2 = dr * dr;
    *(__half2*)((char*)g_G1 + off) = __floats2half2_rn(dr * a1x,  dr * a1y);
    *(__half2*)((char*)g_G2 + off) = __floats2half2_rn(dr * a2x,  dr * a2y);
    *(__half2*)((char*)g_G3 + off) = __floats2half2_rn(dr2 * a3x, dr2 * a3y);
    if (t == 0) g_swn[r] = dr * sw;
}

// ---------------- fused GEMMs (fp16, bulk-copy loader, frozen core) --------
#define STA 0
#define STB 16384
#define STG_SZ 24576
#define MB_OFF 49152
#define SMEM_T (49152 + 32)

__device__ __forceinline__ float ex_relu(float mu, float sig) {
    if (sig <= 0.f) return fmaxf(mu, 0.f);
    float ss = sqrtf(sig);
    float w = mu / ss;
    return ss * (expf(-0.5f * w * w) * 0.3989422804014327f
                 + 0.5f * w * (1.f + erff(w * 0.7071067811865476f)));
}

__device__ __forceinline__ void compute_chunk(uint32_t base, uint32_t aRowOff,
                                              uint32_t bRowOff, uint32_t lhc,
                                              uint32_t swz, float (&acc)[2][4][4]) {
#pragma unroll
    for (int ks = 0; ks < 4; ks++) {
        uint32_t xoff = ((uint32_t)ks * 32 + lhc) ^ swz;
        uint32_t a[2][4], b[2][4];
        ldsm_x4(a[0], base + STA + aRowOff + xoff);
        ldsm_x4(a[1], base + STA + aRowOff + 16*128 + xoff);
        ldsm_x4(b[0], base + STB + bRowOff + xoff);
        ldsm_x4(b[1], base + STB + bRowOff + 16*128 + xoff);
#pragma unroll
        for (int mf = 0; mf < 2; mf++)
#pragma unroll
            for (int nf = 0; nf < 2; nf++) {
                mma_fp16(acc[mf][2*nf],   a[mf], b[nf][0], b[nf][2]);
                mma_fp16(acc[mf][2*nf+1], a[mf], b[nf][1], b[nf][3]);
            }
    }
}

// ---- phase 0: c1 = G1 @ W -> g_C1 (fp16), grid (157, 2) ----
__global__ __launch_bounds__(256, 2) void gemm_c1() {
    const int tile = blockIdx.x, nh = blockIdx.y;
    extern __shared__ __align__(1024) char smem[];
    uint32_t smb = smem_u32(smem);
    int tid = threadIdx.x;
    int wid = tid >> 5, lane = tid & 31;
    int wm = wid >> 1, wn = wid & 1;
    int lrow = lane & 15;
    uint32_t lhc = (uint32_t)(lane >> 4) * 16;
    uint32_t swz = (uint32_t)(lrow & 7) << 4;
    uint32_t aRowOff = (uint32_t)(wm * 32 + lrow) * 128;
    uint32_t bRowOff = (uint32_t)(wn * 32 + lrow) * 128;

    float acc[2][4][4];
#pragma unroll
    for (int i = 0; i < 2; i++)
#pragma unroll
        for (int j = 0; j < 4; j++)
#pragma unroll
            for (int q = 0; q < 4; q++) acc[i][j][q] = 0.f;

    if (tid == 0) { MBAR_INIT(smb + MB_OFF, 1); MBAR_INIT(smb + MB_OFF + 8, 1); }
    __syncthreads();

    auto load_stage = [&](int kc, int buf) {
        if (tid == 0) {
            uint32_t mb = smb + MB_OFF + buf * 8;
            MBAR_EXPTX(mb, 24576);
            bulk_g2s(smb + buf*STG_SZ + STA,
                     (const char*)g_G1 + ((size_t)kc*NTILES + tile)*16384, 16384, mb);
            bulk_g2s(smb + buf*STG_SZ + STB,
                     (const char*)g_Wt + ((size_t)(nh*4 + kc))*8192, 8192, mb);
        }
    };

    load_stage(0, 0);
    load_stage(1, 1);
    for (int ch = 0; ch < 4; ch++) {
        mbar_wait(smb + MB_OFF + (ch & 1)*8, (ch >> 1) & 1);
        compute_chunk(smb + (ch & 1) * STG_SZ, aRowOff, bRowOff, lhc, swz, acc);
        __syncthreads();
        if (ch + 2 < 4) load_stage(ch + 2, ch & 1);
    }

    int cb = nh * 64 + wn * 32 + (lane & 3) * 2;
#pragma unroll
    for (int mf = 0; mf < 2; mf++) {
        int r0 = tile * 128 + wm * 32 + mf * 16 + (lane >> 2);
#pragma unroll
        for (int n8 = 0; n8 < 4; n8++) {
            int c = cb + n8 * 8;
            if (r0 < N_NODES)
                *(__half2*)(g_C1 + (size_t)r0 * FOUT + c) =
                    __floats2half2_rn(acc[mf][n8][0], acc[mf][n8][1]);
            if (r0 + 8 < N_NODES)
                *(__half2*)(g_C1 + (size_t)(r0 + 8) * FOUT + c) =
                    __floats2half2_rn(acc[mf][n8][2], acc[mf][n8][3]);
        }
    }
}

// ---- phase 1: mx/cv GEMMs + ExRelu epilogue -> fp16 partials --------------
__global__ __launch_bounds__(256, 2) void gemm_mix(const float* __restrict__ bias) {
    const int tile = blockIdx.x, nh = blockIdx.y, kk = blockIdx.z;

    extern __shared__ __align__(1024) char smem[];
    uint32_t smb = smem_u32(smem);
    int tid = threadIdx.x;
    int wid = tid >> 5, lane = tid & 31;
    int wm = wid >> 1, wn = wid & 1;
    int lrow = lane & 15;
    uint32_t lhc = (uint32_t)(lane >> 4) * 16;
    uint32_t swz = (uint32_t)(lrow & 7) << 4;
    uint32_t aRowOff = (uint32_t)(wm * 32 + lrow) * 128;
    uint32_t bRowOff = (uint32_t)(wn * 32 + lrow) * 128;
    const int colblk = kk * 2 + nh;

    float mxr[2][4][4], acc[2][4][4];
#pragma unroll
    for (int i = 0; i < 2; i++)
#pragma unroll
        for (int j = 0; j < 4; j++)
#pragma unroll
            for (int q = 0; q < 4; q++) { mxr[i][j][q] = 0.f; acc[i][j][q] = 0.f; }

    if (tid == 0) { MBAR_INIT(smb + MB_OFF, 1); MBAR_INIT(smb + MB_OFF + 8, 1); }
    __syncthreads();

    auto load_stage = [&](int ch, int buf) {
        if (tid == 0) {
            int phase = ch >> 2;
            int kc = ch & 3;
            const char* A = (const char*)(phase ? g_G3 : g_G2);
            const char* B = (const char*)(phase ? g_Wct : g_Wmt);
            uint32_t mb = smb + MB_OFF + buf * 8;
            MBAR_EXPTX(mb, 24576);
            bulk_g2s(smb + buf*STG_SZ + STA,
                     A + ((size_t)kc*NTILES + tile)*16384, 16384, mb);
            bulk_g2s(smb + buf*STG_SZ + STB,
                     B + ((size_t)(colblk*4 + kc))*8192, 8192, mb);
        }
    };

    load_stage(0, 0);
    load_stage(1, 1);
    for (int ch = 0; ch < 8; ch++) {
        mbar_wait(smb + MB_OFF + (ch & 1)*8, (ch >> 1) & 1);
        uint32_t base = smb + (ch & 1) * STG_SZ;
        if (ch < 4)
            compute_chunk(base, aRowOff, bRowOff, lhc, swz, mxr);
        else
            compute_chunk(base, aRowOff, bRowOff, lhc, swz, acc);
        __syncthreads();
        if (ch + 2 < 8) load_stage(ch + 2, ch & 1);
    }

    // epilogue: Part[kk] = gamma_k * exrelu(c1 + mx + swn*bias, cv), plain stores
    int cb = nh * 64 + wn * 32 + (lane & 3) * 2;
    half* part = g_Part + (size_t)kk * N_NODES * FOUT;
#pragma unroll
    for (int mf = 0; mf < 2; mf++) {
#pragma unroll
        for (int rh = 0; rh < 2; rh++) {
            int r = tile * 128 + wm * 32 + mf * 16 + (lane >> 2) + rh * 8;
            if (r >= N_NODES) continue;
            float ga = g_gamma[kk * N_NODES + r];
            float swr = g_swn[r];
#pragma unroll
            for (int n8 = 0; n8 < 4; n8++) {
                int c = cb + n8 * 8;
                float2 c1v = __half22float2(*(const __half2*)(g_C1 + (size_t)r * FOUT + c));
                float2 bv  = *(const float2*)(bias + c);
                float mu0 = c1v.x + mxr[mf][n8][2*rh]   + swr * bv.x;
                float mu1 = c1v.y + mxr[mf][n8][2*rh+1] + swr * bv.y;
                float t0 = ga * ex_relu(mu0, acc[mf][n8][2*rh]);
                float t1 = ga * ex_relu(mu1, acc[mf][n8][2*rh+1]);
                *(__half2*)(part + (size_t)r * FOUT + c) = __floats2half2_rn(t0, t1);
            }
        }
    }
}

// ---- final: out = sum_k Part[k] -------------------------------------------
__global__ __launch_bounds__(256) void final_sum(float* __restrict__ out) {
    int idx = blockIdx.x * 256 + threadIdx.x;     // over N_NODES*FOUT/2
    if (idx >= N_NODES*FOUT/2) return;
    float sx = 0.f, sy = 0.f;
#pragma unroll
    for (int k = 0; k < KMIX; k++) {
        float2 v = __half22float2(
            ((const __half2*)g_Part)[(size_t)k * (N_NODES*FOUT/2) + idx]);
        sx += v.x; sy += v.y;
    }
    ((float2*)out)[idx] = make_float2(sx, sy);
}

// ---------------- launch ---------------------------------------------------
extern "C" void kernel_launch(void* const* d_in, const int* in_sizes, int n_in,
                              void* d_out, int out_size) {
    const float* x       = (const float*)d_in[0];
    const void*  ei      = d_in[1];
    const float* logp    = (const float*)d_in[2];
    const float* means   = (const float*)d_in[3];
    const float* logvars = (const float*)d_in[4];
    const float* weight  = (const float*)d_in[5];
    const float* bias    = (const float*)d_in[6];
    float*       out     = (float*)d_out;

    cudaFuncSetAttribute(gemm_c1,  cudaFuncAttributeMaxDynamicSharedMemorySize, SMEM_T);
    cudaFuncSetAttribute(gemm_mix, cudaFuncAttributeMaxDynamicSharedMemorySize, SMEM_T);

    setup_all<<<(KO*FIN + 255)/256, 256>>>((const int*)ei, means, logvars, weight);
    prep_and_count<<<PREPB + CNTB, FIN>>>(x, means, logp, ei);
    compute_offsets<<<(N_NODES + 255)/256, 256>>>();
    scatter_edges<<<(N_EDGES/2 + 255)/256, 256>>>(ei);
    spmm_kernel<<<N_NODES, 128>>>();

    gemm_c1 <<<dim3(NTILES, 2), 256, SMEM_T>>>();
    gemm_mix<<<dim3(NTILES, 2, KMIX), 256, SMEM_T>>>(bias);
    final_sum<<<(N_NODES*FOUT/2 + 255)/256, 256>>>(out);
}